// round 13
// baseline (speedup 1.0000x reference)
#include <cuda_runtime.h>
#include <cuda_bf16.h>
#include <cstdint>
#include <cstddef>

// Problem constants
#define BB   64
#define LL   49
#define TT   20
#define VV   10000
#define EE   512
#define ENCD 2048
#define DD   512
#define AA   512
#define NG   2048
#define KC2  2560    // ENC + D

#define SMEMB 51200     // fp32 gemm dynamic smem
#define SMEM_GT 49152   // gates_step dynamic smem

// ---------------- device scratch (static, no allocations) ----------------
__device__ float g_mean[BB * ENCD];
__device__ float g_encproj[BB * LL * AA];
__device__ float g_bcat[NG];
__device__ float g_Eall[TT * BB * EE];
__device__ float g_Gemb[TT * BB * NG];
__device__ float g_h[BB * DD];
__device__ float g_c[BB * DD];
__device__ float g_X2[BB * KC2];
__device__ float g_hall[TT * BB * DD];
__device__ float g_ph[8 * BB * DD];
__device__ float g_pc[8 * BB * DD];
__device__ float g_gpart[8 * BB * NG];
// pre-split bf16 weights (hi/lo), K-contiguous rows
__device__ __nv_bfloat16 g_Wch_h[NG * KC2],  g_Wch_l[NG * KC2];    // (2048 x 2560)
__device__ __nv_bfloat16 g_Wout_h[VV * DD],  g_Wout_l[VV * DD];    // (10000 x 512)
__device__ __nv_bfloat16 g_Wenc_h[AA * ENCD], g_Wenc_l[AA * ENCD]; // (512 x 2048)
__device__ __nv_bfloat16 g_Wemb_h[NG * EE],  g_Wemb_l[NG * EE];    // (2048 x 512)

// ---------------- helpers ----------------
__device__ __forceinline__ uint32_t smem_u32(const void* p) {
    uint32_t a;
    asm("{ .reg .u64 t; cvta.to.shared.u64 t, %1; cvt.u32.u64 %0, t; }" : "=r"(a) : "l"(p));
    return a;
}
__device__ __forceinline__ uint32_t sw128(uint32_t off) { return off ^ ((off >> 3) & 0x70); }

__device__ __forceinline__ void split2(float x, float y, uint32_t& hi, uint32_t& lo) {
    __nv_bfloat16 hx = __float2bfloat16_rn(x), hy = __float2bfloat16_rn(y);
    __nv_bfloat16 lx = __float2bfloat16_rn(x - __bfloat162float(hx));
    __nv_bfloat16 ly = __float2bfloat16_rn(y - __bfloat162float(hy));
    __nv_bfloat162 h; h.x = hx; h.y = hy;
    __nv_bfloat162 l; l.x = lx; l.y = ly;
    hi = *(uint32_t*)&h;
    lo = *(uint32_t*)&l;
}
__device__ __forceinline__ void split4(float4 v, uint2& h, uint2& l) {
    split2(v.x, v.y, h.x, l.x);
    split2(v.z, v.w, h.y, l.y);
}

__device__ __forceinline__ void ldsm4(uint32_t a, uint32_t& r0, uint32_t& r1,
                                      uint32_t& r2, uint32_t& r3) {
    asm volatile("ldmatrix.sync.aligned.m8n8.x4.shared.b16 {%0,%1,%2,%3}, [%4];"
                 : "=r"(r0), "=r"(r1), "=r"(r2), "=r"(r3) : "r"(a));
}
__device__ __forceinline__ void mma16816(float* d, const uint32_t* a, const uint32_t* b) {
    asm volatile("mma.sync.aligned.m16n8k16.row.col.f32.bf16.bf16.f32 "
                 "{%0,%1,%2,%3}, {%4,%5,%6,%7}, {%8,%9}, {%0,%1,%2,%3};"
                 : "+f"(d[0]), "+f"(d[1]), "+f"(d[2]), "+f"(d[3])
                 : "r"(a[0]), "r"(a[1]), "r"(a[2]), "r"(a[3]), "r"(b[0]), "r"(b[1]));
}

// 64x128 triple-term bf16 mma over one 64-wide K chunk (tiles in smem at given offsets)
__device__ __forceinline__ void mma_c64(uint32_t sb, uint32_t aHi, uint32_t aLo,
                                        uint32_t bHi, uint32_t bLo,
                                        float acc[2][4][4], int lane, int wid)
{
    const int wm = (wid & 1) * 32, wn = (wid >> 1) * 32;
    const int lr = lane & 7, lm = lane >> 3;
    #pragma unroll
    for (int kk = 0; kk < 4; kk++) {
        uint32_t ah[2][4], al[2][4];
        #pragma unroll
        for (int mt = 0; mt < 2; mt++) {
            uint32_t off = sw128((uint32_t)(
                (wm + mt * 16 + (lm & 1) * 8 + lr) * 128 + kk * 32 + (lm >> 1) * 16));
            ldsm4(sb + aHi + off, ah[mt][0], ah[mt][1], ah[mt][2], ah[mt][3]);
            ldsm4(sb + aLo + off, al[mt][0], al[mt][1], al[mt][2], al[mt][3]);
        }
        #pragma unroll
        for (int j = 0; j < 2; j++) {
            uint32_t offb = sw128((uint32_t)(
                (wn + j * 16 + (lm >> 1) * 8 + lr) * 128 + kk * 32 + (lm & 1) * 16));
            uint32_t bh[4], bl[4];
            ldsm4(sb + bHi + offb, bh[0], bh[1], bh[2], bh[3]);
            ldsm4(sb + bLo + offb, bl[0], bl[1], bl[2], bl[3]);
            #pragma unroll
            for (int mt = 0; mt < 2; mt++) {
                #pragma unroll
                for (int h = 0; h < 2; h++) {
                    float* d = acc[mt][j * 2 + h];
                    mma16816(d, ah[mt], bh + 2 * h);
                    mma16816(d, ah[mt], bl + 2 * h);
                    mma16816(d, al[mt], bh + 2 * h);
                }
            }
        }
    }
}

__device__ __forceinline__ float sigmoidf(float x) { return 1.f / (1.f + expf(-x)); }
__device__ __forceinline__ float lstm_h(float si, float sf, float sg, float so,
                                        float co, float& cn) {
    float i = sigmoidf(si), f = sigmoidf(sf), o = sigmoidf(so), g = tanhf(sg);
    cn = f * co + i * g;
    return o * tanhf(cn);
}

// ---------------- fused step: finalize(t-1) + dec_proj(t) + attention(t) ----------------
// 64 blocks, one per batch row. Block b owns row b exclusively (c, hall, X2 writes).
__global__ void __launch_bounds__(256, 1)
fused_step(const float* __restrict__ enc_out,
           const float* __restrict__ W_dec,     // (D x A) row-major, fp32
           const float* __restrict__ b_dec_att,
           const float* __restrict__ w_full,
           const float* __restrict__ b_full,
           float* __restrict__ alphas_out, int t)
{
    __shared__ float sh_h[DD];
    __shared__ float sh_dec[AA];
    __shared__ float sh_w[AA];
    __shared__ float sh_sc[64];
    __shared__ float sh_part[2][AA];

    const int b = blockIdx.x, tid = threadIdx.x;
    const int warp = tid >> 5, lane = tid & 31;

    // ---- 1. finalize step t-1 (or load h0 at t==0)
    if (t == 0) {
        for (int d = tid; d < DD; d += 256) sh_h[d] = g_h[b * DD + d];
    } else {
        const float* ge = g_Gemb + ((size_t)(t - 1) * BB + b) * NG;
        #pragma unroll
        for (int u = 0; u < 2; u++) {
            const int d = tid + u * 256;
            float gi = g_bcat[d]        + ge[d];
            float gf = g_bcat[512 + d]  + ge[512 + d];
            float gg = g_bcat[1024 + d] + ge[1024 + d];
            float go = g_bcat[1536 + d] + ge[1536 + d];
            #pragma unroll
            for (int z = 0; z < 8; z++) {
                const float* gp = g_gpart + (size_t)(z * BB + b) * NG;
                gi += gp[d]; gf += gp[512 + d]; gg += gp[1024 + d]; go += gp[1536 + d];
            }
            float cn;
            float h = lstm_h(gi, gf, gg, go, g_c[b * DD + d], cn);
            g_c[b * DD + d] = cn;
            g_hall[((size_t)(t - 1) * BB + b) * DD + d] = h;
            g_X2[(size_t)b * KC2 + ENCD + d] = h;
            sh_h[d] = h;
        }
    }
    if (t == TT) return;

    for (int a = tid; a < AA; a += 256) sh_w[a] = w_full[a];
    __syncthreads();

    // ---- 2. dec_proj: dec[a] = b_dec[a] + sum_d h[d] * W_dec[d][a]
    // two halves of d-range; 128 threads per half, float4 over a.
    {
        const int half = tid >> 7;            // 0/1 -> d in [half*256, +256)
        const int a4 = (tid & 127) * 4;
        const float* Wp = W_dec + (size_t)(half * 256) * AA + a4;
        float4 acc = make_float4(0.f, 0.f, 0.f, 0.f);
        #pragma unroll 4
        for (int d = 0; d < 256; d++) {
            const float hv = sh_h[half * 256 + d];
            const float4 w = *(const float4*)(Wp + (size_t)d * AA);
            acc.x = fmaf(hv, w.x, acc.x);
            acc.y = fmaf(hv, w.y, acc.y);
            acc.z = fmaf(hv, w.z, acc.z);
            acc.w = fmaf(hv, w.w, acc.w);
        }
        *(float4*)&sh_part[half][a4] = acc;
    }
    __syncthreads();
    if (tid < 128) {
        const int a4 = tid * 4;
        float4 p0 = *(const float4*)&sh_part[0][a4];
        float4 p1 = *(const float4*)&sh_part[1][a4];
        float4 bd = *(const float4*)&b_dec_att[a4];
        float4 r;
        r.x = p0.x + p1.x + bd.x;
        r.y = p0.y + p1.y + bd.y;
        r.z = p0.z + p1.z + bd.z;
        r.w = p0.w + p1.w + bd.w;
        *(float4*)&sh_dec[a4] = r;
    }
    __syncthreads();

    // ---- 3. scores: s[l] = w . relu(encproj[b,l,:] + dec) + b_full
    for (int l = warp; l < LL; l += 8) {
        const float4* ep = (const float4*)(g_encproj + ((size_t)b * LL + l) * AA);
        float s = 0.f;
        #pragma unroll
        for (int a4 = lane; a4 < 128; a4 += 32) {
            float4 e4 = ep[a4];
            float4 dv = *(const float4*)&sh_dec[a4 * 4];
            float4 wv = *(const float4*)&sh_w[a4 * 4];
            s = fmaf(fmaxf(e4.x + dv.x, 0.f), wv.x, s);
            s = fmaf(fmaxf(e4.y + dv.y, 0.f), wv.y, s);
            s = fmaf(fmaxf(e4.z + dv.z, 0.f), wv.z, s);
            s = fmaf(fmaxf(e4.w + dv.w, 0.f), wv.w, s);
        }
        #pragma unroll
        for (int o = 16; o; o >>= 1) s += __shfl_xor_sync(0xffffffffu, s, o);
        if (lane == 0) sh_sc[l] = s + b_full[0];
    }
    __syncthreads();

    // ---- 4. softmax over L=49
    if (warp == 0) {
        float v0 = (lane < LL) ? sh_sc[lane] : -1e30f;
        float v1 = (lane + 32 < LL) ? sh_sc[lane + 32] : -1e30f;
        float mx = fmaxf(v0, v1);
        #pragma unroll
        for (int o = 16; o; o >>= 1) mx = fmaxf(mx, __shfl_xor_sync(0xffffffffu, mx, o));
        float e0 = (lane < LL) ? expf(v0 - mx) : 0.f;
        float e1 = (lane + 32 < LL) ? expf(v1 - mx) : 0.f;
        float ssum = e0 + e1;
        #pragma unroll
        for (int o = 16; o; o >>= 1) ssum += __shfl_xor_sync(0xffffffffu, ssum, o);
        float inv = 1.f / ssum;
        if (lane < LL) sh_sc[lane] = e0 * inv;
        if (lane + 32 < LL) sh_sc[lane + 32] = e1 * inv;
    }
    __syncthreads();

    for (int l = tid; l < LL; l += 256)
        alphas_out[((size_t)b * TT + t) * LL + l] = sh_sc[l];

    // ---- 5. context: X2[b, e] = sum_l alpha[l] * enc_out[b, l, e]  (float4 over e)
    #pragma unroll
    for (int rep = 0; rep < 2; rep++) {
        const int e4 = tid + rep * 256;       // float4 index, 512 total -> e = e4*4
        const float4* eb = (const float4*)(enc_out + (size_t)b * LL * ENCD) + e4;
        float4 s = make_float4(0.f, 0.f, 0.f, 0.f);
        #pragma unroll 7
        for (int l = 0; l < LL; l++) {
            float4 v = eb[(size_t)l * (ENCD / 4)];
            float al = sh_sc[l];
            s.x = fmaf(al, v.x, s.x);
            s.y = fmaf(al, v.y, s.y);
            s.z = fmaf(al, v.z, s.z);
            s.w = fmaf(al, v.w, s.w);
        }
        *(float4*)&g_X2[(size_t)b * KC2 + e4 * 4] = s;
    }
}

// ---------------- gates split-K mma (grid 16 x 8) ----------------
// smem: A hi @ 0, lo @ 8192, B hi @ 16384, lo @ 32768
__global__ void __launch_bounds__(256, 1)
gates_step()
{
    extern __shared__ __align__(1024) char smem[];
    const int tid = threadIdx.x;
    const int lane = tid & 31, wid = tid >> 5;
    const int n = blockIdx.x, z = blockIdx.y;
    const uint32_t sb = smem_u32(smem);

    float acc[2][4][4];
    #pragma unroll
    for (int i = 0; i < 2; i++)
        #pragma unroll
        for (int j = 0; j < 4; j++)
            #pragma unroll
            for (int q = 0; q < 4; q++) acc[i][j][q] = 0.f;

    const int kbase = z * 320;
    for (int k64 = 0; k64 < 5; k64++) {
        const int kc = kbase + k64 * 64;
        #pragma unroll
        for (int it = 0; it < 4; it++) {
            int q = tid + 256 * it;        // 0..1023 float4
            int r = q >> 4, f4 = q & 15;
            float4 v = *(const float4*)&g_X2[r * 2560 + kc + f4 * 4];
            uint2 hh, ll; split4(v, hh, ll);
            uint32_t so = sw128((uint32_t)(r * 128 + f4 * 8));
            *(uint2*)(smem + so) = hh;
            *(uint2*)(smem + 8192 + so) = ll;
        }
        #pragma unroll
        for (int it = 0; it < 4; it++) {
            int q = tid + 256 * it;        // 0..1023 uint4
            int r = q >> 3, c16 = q & 7;
            size_t gi = (size_t)(n * 128 + r) * 2560 + kc + c16 * 8;
            uint4 vh = *(const uint4*)&g_Wch_h[gi];
            uint4 vl = *(const uint4*)&g_Wch_l[gi];
            uint32_t so = sw128((uint32_t)(r * 128 + c16 * 16));
            *(uint4*)(smem + 16384 + so) = vh;
            *(uint4*)(smem + 32768 + so) = vl;
        }
        __syncthreads();
        mma_c64(sb, 0, 8192, 16384, 32768, acc, lane, wid);
        __syncthreads();
    }
    const int wm = (wid & 1) * 32, wn = (wid >> 1) * 32;
    const int rl = lane >> 2, cl = (lane & 3) * 2;
    float* gp = g_gpart + (size_t)z * 64 * 2048;
    #pragma unroll
    for (int mt = 0; mt < 2; mt++) {
        #pragma unroll
        for (int nt = 0; nt < 4; nt++) {
            int c = n * 128 + wn + nt * 8 + cl;
            #pragma unroll
            for (int h = 0; h < 2; h++) {
                int r = wm + mt * 16 + rl + h * 8;
                float2 v = make_float2(acc[mt][nt][h * 2], acc[mt][nt][h * 2 + 1]);
                *(float2*)&gp[r * 2048 + c] = v;
            }
        }
    }
}

// ---------------- batch mma GEMM: C(MxN) = A(MxK) * B(NxK)^T ----------------
template<int MODE>
__global__ void __launch_bounds__(256)
mma_gemm(const float* __restrict__ A, int lda,
         const __nv_bfloat16* __restrict__ Bhi, const __nv_bfloat16* __restrict__ Blo,
         int ldb, const float* __restrict__ bias,
         float* __restrict__ C, int ldc, int M, int N, int K)
{
    extern __shared__ __align__(1024) char smem[];
    const uint32_t sb = smem_u32(smem);
    const uint32_t AHI = 0, ALO = 16384, BHI = 32768, BLO = 49152;

    const int tid = threadIdx.x, lane = tid & 31, wid = tid >> 5;
    const int m0 = blockIdx.y * 128, n0 = blockIdx.x * 128;

    const int wm = (wid & 3) * 32;
    const int wn = (wid >> 2) * 64;
    const int lr = lane & 7, lm = lane >> 3;

    float acc[2][8][4];
    #pragma unroll
    for (int i = 0; i < 2; i++)
        #pragma unroll
        for (int j = 0; j < 8; j++)
            #pragma unroll
            for (int q = 0; q < 4; q++) acc[i][j][q] = 0.f;

    for (int kc = 0; kc < K; kc += 64) {
        #pragma unroll
        for (int p = 0; p < 4; p++) {
            const int i = tid + 256 * p;
            const int row = i >> 3, c16 = i & 7;
            const int gm = m0 + row;
            float4 v0 = make_float4(0.f, 0.f, 0.f, 0.f), v1 = v0;
            if (gm < M) {
                const float* ap = A + (size_t)gm * lda + kc + c16 * 8;
                v0 = *(const float4*)ap;
                v1 = *(const float4*)(ap + 4);
            }
            uint4 hv, lv;
            split2(v0.x, v0.y, hv.x, lv.x);
            split2(v0.z, v0.w, hv.y, lv.y);
            split2(v1.x, v1.y, hv.z, lv.z);
            split2(v1.z, v1.w, hv.w, lv.w);
            const uint32_t so = sw128((uint32_t)(row * 128 + c16 * 16));
            *(uint4*)(smem + AHI + so) = hv;
            *(uint4*)(smem + ALO + so) = lv;
        }
        #pragma unroll
        for (int p = 0; p < 4; p++) {
            const int i = tid + 256 * p;
            const int row = i >> 3, c16 = i & 7;
            const int gn = n0 + row;
            uint4 vh = make_uint4(0, 0, 0, 0), vl = vh;
            if (gn < N) {
                vh = *(const uint4*)(Bhi + (size_t)gn * ldb + kc + c16 * 8);
                vl = *(const uint4*)(Blo + (size_t)gn * ldb + kc + c16 * 8);
            }
            const uint32_t so = sw128((uint32_t)(row * 128 + c16 * 16));
            *(uint4*)(smem + BHI + so) = vh;
            *(uint4*)(smem + BLO + so) = vl;
        }
        __syncthreads();

        #pragma unroll
        for (int kk = 0; kk < 4; kk++) {
            uint32_t ah[2][4], al[2][4];
            #pragma unroll
            for (int mt = 0; mt < 2; mt++) {
                const uint32_t off = sw128((uint32_t)(
                    (wm + mt * 16 + (lm & 1) * 8 + lr) * 128 + kk * 32 + (lm >> 1) * 16));
                ldsm4(sb + AHI + off, ah[mt][0], ah[mt][1], ah[mt][2], ah[mt][3]);
                ldsm4(sb + ALO + off, al[mt][0], al[mt][1], al[mt][2], al[mt][3]);
            }
            #pragma unroll
            for (int j = 0; j < 4; j++) {
                const uint32_t offb = sw128((uint32_t)(
                    (wn + j * 16 + (lm >> 1) * 8 + lr) * 128 + kk * 32 + (lm & 1) * 16));
                uint32_t bh[4], bl[4];
                ldsm4(sb + BHI + offb, bh[0], bh[1], bh[2], bh[3]);
                ldsm4(sb + BLO + offb, bl[0], bl[1], bl[2], bl[3]);
                #pragma unroll
                for (int mt = 0; mt < 2; mt++) {
                    #pragma unroll
                    for (int h = 0; h < 2; h++) {
                        float* d = acc[mt][j * 2 + h];
                        mma16816(d, ah[mt], bh + 2 * h);
                        mma16816(d, ah[mt], bl + 2 * h);
                        mma16816(d, al[mt], bh + 2 * h);
                    }
                }
            }
        }
        __syncthreads();
    }

    const int r_lane = lane >> 2;
    const int c_lane = (lane & 3) * 2;
    #pragma unroll
    for (int mt = 0; mt < 2; mt++) {
        #pragma unroll
        for (int nt = 0; nt < 8; nt++) {
            const int c = n0 + wn + nt * 8 + c_lane;
            if (c >= N) continue;
            const float b0 = bias ? bias[c] : 0.f;
            const float b1 = bias ? bias[c + 1] : 0.f;
            #pragma unroll
            for (int hh = 0; hh < 2; hh++) {
                const int r = m0 + wm + mt * 16 + r_lane + hh * 8;
                if (r >= M) continue;
                float2 v;
                v.x = acc[mt][nt][hh * 2 + 0] + b0;
                v.y = acc[mt][nt][hh * 2 + 1] + b1;
                if (MODE == 0) {
                    *(float2*)&C[(size_t)r * ldc + c] = v;
                } else {
                    const int tq = r >> 6, bq = r & 63;
                    *(float2*)&C[((size_t)bq * TT + tq) * VV + c] = v;
                }
            }
        }
    }
}

// ---------------- packed fp32x2 helpers ----------------
#define FMA2(D,Aq,Bq,Cq) asm("fma.rn.f32x2 %0, %1, %2, %3;" : "=l"(D) : "l"(Aq), "l"(Bq), "l"(Cq))
#define PACK2(D,LO,HI)   asm("mov.b64 %0, {%1, %2};" : "=l"(D) : "f"(LO), "f"(HI))
#define UNPK2(LO,HI,S)   asm("mov.b64 {%0, %1}, %2;" : "=f"(LO), "=f"(HI) : "l"(S))

// ---------------- fp32 FFMA2 GEMM (h0/c0 init only, NN layout) ----------------
__global__ void gemm_f32(const float* __restrict__ A, int lda,
                         const float* __restrict__ B, int ldb,
                         float* __restrict__ C, int M, int N, int K)
{
    extern __shared__ float sm[];
    float* As = sm;
    float* Bs = sm + 2 * 32 * 68;

    const int tid = threadIdx.x;
    const int m0  = blockIdx.y * 64;
    const int n0  = blockIdx.x * 128;
    const int k0base = blockIdx.z * K;
    if (gridDim.z > 1) C += (size_t)blockIdx.z * (size_t)M * (size_t)N;

    const int lane = tid & 31, warp = tid >> 5, tx = lane;
    const int a_kp = tid & 7, a_mr = tid >> 3;
    const int b_n4 = tid & 31, b_kr = tid >> 5;

    float4 Ag[2], Bg[4];
    const float4 z4 = make_float4(0.f, 0.f, 0.f, 0.f);

    unsigned long long acc2[4][4];
    #pragma unroll
    for (int i = 0; i < 4; i++)
        #pragma unroll
        for (int j = 0; j < 4; j++) acc2[i][j] = 0ull;

    {
        const int k0 = k0base;
        #pragma unroll
        for (int p = 0; p < 2; p++) {
            const int gm = m0 + a_mr + p * 32;
            Ag[p] = (gm < M) ? *(const float4*)(A + (size_t)gm * lda + k0 + a_kp * 4) : z4;
        }
        #pragma unroll
        for (int p = 0; p < 4; p++) {
            const int kk = b_kr + p * 8;
            const int gn = n0 + b_n4 * 4;
            Bg[p] = (gn + 3 < N) ? *(const float4*)(B + (size_t)(k0 + kk) * ldb + gn) : z4;
        }
        float* Ad = As;
        #pragma unroll
        for (int p = 0; p < 2; p++) {
            const int m = a_mr + p * 32;
            Ad[(a_kp * 4 + 0) * 68 + m] = Ag[p].x;
            Ad[(a_kp * 4 + 1) * 68 + m] = Ag[p].y;
            Ad[(a_kp * 4 + 2) * 68 + m] = Ag[p].z;
            Ad[(a_kp * 4 + 3) * 68 + m] = Ag[p].w;
        }
        float* Bd = Bs;
        #pragma unroll
        for (int p = 0; p < 4; p++)
            *(float4*)&Bd[(b_kr + p * 8) * 132 + b_n4 * 4] = Bg[p];
    }
    __syncthreads();

    int cur = 0;
    for (int kt = 0; kt < K; kt += 32) {
        const bool has_next = (kt + 32 < K);
        if (has_next) {
            const int k0 = k0base + kt + 32;
            #pragma unroll
            for (int p = 0; p < 2; p++) {
                const int gm = m0 + a_mr + p * 32;
                Ag[p] = (gm < M) ? *(const float4*)(A + (size_t)gm * lda + k0 + a_kp * 4) : z4;
            }
            #pragma unroll
            for (int p = 0; p < 4; p++) {
                const int kk = b_kr + p * 8;
                const int gn = n0 + b_n4 * 4;
                Bg[p] = (gn + 3 < N) ? *(const float4*)(B + (size_t)(k0 + kk) * ldb + gn) : z4;
            }
        }
        const float* Ab = As + cur * 2176;
        const float* Bb = Bs + cur * 4224;
        #pragma unroll
        for (int kk = 0; kk < 32; kk++) {
            const float* Ak = Ab + kk * 68 + warp * 8;
            const float* Bk = Bb + kk * 132 + tx * 4;
            ulonglong2 av0 = *(const ulonglong2*)(Ak);
            ulonglong2 av1 = *(const ulonglong2*)(Ak + 4);
            float4 bv = *(const float4*)(Bk);
            unsigned long long a2[4] = {av0.x, av0.y, av1.x, av1.y};
            unsigned long long b2[4];
            PACK2(b2[0], bv.x, bv.x);
            PACK2(b2[1], bv.y, bv.y);
            PACK2(b2[2], bv.z, bv.z);
            PACK2(b2[3], bv.w, bv.w);
            #pragma unroll
            for (int i = 0; i < 4; i++)
                #pragma unroll
                for (int j = 0; j < 4; j++)
                    FMA2(acc2[i][j], a2[i], b2[j], acc2[i][j]);
        }
        if (has_next) {
            const int nb = cur ^ 1;
            float* Ad = As + nb * 2176;
            #pragma unroll
            for (int p = 0; p < 2; p++) {
                const int m = a_mr + p * 32;
                Ad[(a_kp * 4 + 0) * 68 + m] = Ag[p].x;
                Ad[(a_kp * 4 + 1) * 68 + m] = Ag[p].y;
                Ad[(a_kp * 4 + 2) * 68 + m] = Ag[p].z;
                Ad[(a_kp * 4 + 3) * 68 + m] = Ag[p].w;
            }
            float* Bd = Bs + nb * 4224;
            #pragma unroll
            for (int p = 0; p < 4; p++)
                *(float4*)&Bd[(b_kr + p * 8) * 132 + b_n4 * 4] = Bg[p];
        }
        __syncthreads();
        cur ^= 1;
    }

    #pragma unroll
    for (int ip = 0; ip < 4; ip++) {
        const int r0 = m0 + warp * 8 + ip * 2;
        #pragma unroll
        for (int j = 0; j < 4; j++) {
            const int c = n0 + tx * 4 + j;
            if (c >= N) continue;
            float v0, v1;
            UNPK2(v0, v1, acc2[ip][j]);
            if (r0 < M)     C[(size_t)r0 * N + c]       = v0;
            if (r0 + 1 < M) C[(size_t)(r0 + 1) * N + c] = v1;
        }
    }
}

// ---------------- prep: split static weights to bf16 hi/lo ----------------
__global__ void prep_kernel(const float* __restrict__ W_ih, const float* __restrict__ W_hh,
                            const float* __restrict__ b_ih, const float* __restrict__ b_hh)
{
    const long total = (long)NG * KC2;
    for (long idx = (long)blockIdx.x * blockDim.x + threadIdx.x; idx < total;
         idx += (long)gridDim.x * blockDim.x) {
        int j = (int)(idx / KC2);
        int k = (int)(idx % KC2);
        float v = (k < ENCD) ? W_ih[(size_t)j * 2560 + 512 + k]
                             : W_hh[(size_t)j * 512 + (k - ENCD)];
        __nv_bfloat16 h = __float2bfloat16_rn(v);
        g_Wch_h[idx] = h;
        g_Wch_l[idx] = __float2bfloat16_rn(v - __bfloat162float(h));
    }
    const long te = (long)NG * EE;
    for (long idx = (long)blockIdx.x * blockDim.x + threadIdx.x; idx < te;
         idx += (long)gridDim.x * blockDim.x) {
        int j = (int)(idx / EE);
        int e = (int)(idx % EE);
        float v = W_ih[(size_t)j * 2560 + e];
        __nv_bfloat16 h = __float2bfloat16_rn(v);
        g_Wemb_h[idx] = h;
        g_Wemb_l[idx] = __float2bfloat16_rn(v - __bfloat162float(h));
    }
    int idx = blockIdx.x * blockDim.x + threadIdx.x;
    if (idx < NG) g_bcat[idx] = b_ih[idx] + b_hh[idx];
}

// transpose (Kd x Nd) -> (Nd x Kd) with bf16 hi/lo split
__global__ void transpose_split(const float* __restrict__ in,
                                __nv_bfloat16* __restrict__ oh,
                                __nv_bfloat16* __restrict__ ol, int Kd, int Nd)
{
    __shared__ float tile[32][33];
    const int kb = blockIdx.y * 32, nb = blockIdx.x * 32;
    const int tx = threadIdx.x, ty = threadIdx.y;  // 32 x 8
    #pragma unroll
    for (int p = 0; p < 4; p++) {
        const int k = kb + ty + p * 8, n = nb + tx;
        if (k < Kd && n < Nd) tile[ty + p * 8][tx] = in[(size_t)k * Nd + n];
    }
    __syncthreads();
    #pragma unroll
    for (int p = 0; p < 4; p++) {
        const int n = nb + ty + p * 8, k = kb + tx;
        if (n < Nd && k < Kd) {
            float v = tile[tx][ty + p * 8];
            __nv_bfloat16 h = __float2bfloat16_rn(v);
            oh[(size_t)n * Kd + k] = h;
            ol[(size_t)n * Kd + k] = __float2bfloat16_rn(v - __bfloat162float(h));
        }
    }
}

// ---------------- small kernels ----------------
__global__ void gather_emb(const int* __restrict__ captions,
                           const float* __restrict__ emb_table)
{
    int idx = blockIdx.x * blockDim.x + threadIdx.x;
    if (idx >= TT * BB * EE) return;
    int e  = idx & 511;
    int rb = idx >> 9;
    int tq = rb >> 6, bq = rb & 63;
    g_Eall[idx] = emb_table[(size_t)captions[bq * TT + tq] * EE + e];
}

__global__ void mean_kernel(const float* __restrict__ enc_out)
{
    const int b = blockIdx.x, tid = threadIdx.x;
    for (int e = tid; e < ENCD; e += 256) {
        const float* p = enc_out + (size_t)b * LL * ENCD + e;
        float s = 0.f;
        #pragma unroll 7
        for (int l = 0; l < LL; l++) s += p[(size_t)l * ENCD];
        g_mean[b * ENCD + e] = s * (1.f / (float)LL);
    }
}

__global__ void init_reduce(const float* __restrict__ b_init_h,
                            const float* __restrict__ b_init_c)
{
    int idx = blockIdx.x * blockDim.x + threadIdx.x;
    int b = idx >> 9, d = idx & 511;
    float h = b_init_h[d], c = b_init_c[d];
    #pragma unroll
    for (int z = 0; z < 8; z++) {
        h += g_ph[z * (BB * DD) + idx];
        c += g_pc[z * (BB * DD) + idx];
    }
    g_h[idx] = h;
    g_c[idx] = c;
    g_X2[(size_t)b * KC2 + ENCD + d] = h;
}

// ---------------- host launch ----------------
extern "C" void kernel_launch(void* const* d_in, const int* in_sizes, int n_in,
                              void* d_out, int out_size)
{
    const float* enc_out    = (const float*)d_in[0];
    const int*   captions   = (const int*)  d_in[1];
    const float* emb_table  = (const float*)d_in[2];
    const float* W_enc_att  = (const float*)d_in[3];
    const float* b_enc_att  = (const float*)d_in[4];
    const float* W_dec_att  = (const float*)d_in[5];
    const float* b_dec_att  = (const float*)d_in[6];
    const float* w_full     = (const float*)d_in[7];
    const float* b_full     = (const float*)d_in[8];
    const float* W_ih       = (const float*)d_in[9];
    const float* b_ih       = (const float*)d_in[10];
    const float* W_hh       = (const float*)d_in[11];
    const float* b_hh       = (const float*)d_in[12];
    const float* W_init_h   = (const float*)d_in[13];
    const float* b_init_h   = (const float*)d_in[14];
    const float* W_init_c   = (const float*)d_in[15];
    const float* b_init_c   = (const float*)d_in[16];
    const float* W_out      = (const float*)d_in[17];
    const float* b_out      = (const float*)d_in[18];
    float* out = (float*)d_out;
    float* alphas = out + (size_t)BB * TT * VV;

    cudaFuncSetAttribute(gemm_f32, cudaFuncAttributeMaxDynamicSharedMemorySize, SMEMB);
    cudaFuncSetAttribute(mma_gemm<0>, cudaFuncAttributeMaxDynamicSharedMemorySize, 65536);
    cudaFuncSetAttribute(mma_gemm<1>, cudaFuncAttributeMaxDynamicSharedMemorySize, 65536);
    cudaFuncSetAttribute(gates_step, cudaFuncAttributeMaxDynamicSharedMemorySize, SMEM_GT);

    float *p_mean, *p_Eall, *p_Gemb, *p_hall, *p_ph, *p_pc, *p_encproj;
    __nv_bfloat16 *pWout_h, *pWout_l, *pWenc_h, *pWenc_l, *pWemb_h, *pWemb_l;
    cudaGetSymbolAddress((void**)&p_mean,    g_mean);
    cudaGetSymbolAddress((void**)&p_Eall,    g_Eall);
    cudaGetSymbolAddress((void**)&p_Gemb,    g_Gemb);
    cudaGetSymbolAddress((void**)&p_hall,    g_hall);
    cudaGetSymbolAddress((void**)&p_ph,      g_ph);
    cudaGetSymbolAddress((void**)&p_pc,      g_pc);
    cudaGetSymbolAddress((void**)&p_encproj, g_encproj);
    cudaGetSymbolAddress((void**)&pWout_h,   g_Wout_h);
    cudaGetSymbolAddress((void**)&pWout_l,   g_Wout_l);
    cudaGetSymbolAddress((void**)&pWenc_h,   g_Wenc_h);
    cudaGetSymbolAddress((void**)&pWenc_l,   g_Wenc_l);
    cudaGetSymbolAddress((void**)&pWemb_h,   g_Wemb_h);
    cudaGetSymbolAddress((void**)&pWemb_l,   g_Wemb_l);

    // ---- one-time setup
    prep_kernel<<<4096, 256>>>(W_ih, W_hh, b_ih, b_hh);
    gather_emb<<<2560, 256>>>(captions, emb_table);
    mean_kernel<<<BB, 256>>>(enc_out);
    transpose_split<<<dim3((VV + 31) / 32, (DD + 31) / 32), dim3(32, 8)>>>(W_out, pWout_h, pWout_l, DD, VV);
    transpose_split<<<dim3((AA + 31) / 32, (ENCD + 31) / 32), dim3(32, 8)>>>(W_enc_att, pWenc_h, pWenc_l, ENCD, AA);

    // Gemb (1280 x 2048) = Eall(1280x512) @ Wemb(2048x512)^T
    mma_gemm<0><<<dim3(16, 10), 256, 65536>>>(p_Eall, EE, pWemb_h, pWemb_l, EE, nullptr,
                                              p_Gemb, NG, TT * BB, NG, EE);
    // h0/c0 (fp32 path, split-K 8)
    gemm_f32<<<dim3(4, 1, 8), 256, SMEMB>>>(p_mean, ENCD, W_init_h, DD, p_ph, BB, DD, 256);
    gemm_f32<<<dim3(4, 1, 8), 256, SMEMB>>>(p_mean, ENCD, W_init_c, DD, p_pc, BB, DD, 256);
    init_reduce<<<128, 256>>>(b_init_h, b_init_c);
    // enc_proj (3136 x 512) = enc_out(3136x2048) @ Wenc(512x2048)^T + bias
    mma_gemm<0><<<dim3(4, 25), 256, 65536>>>(enc_out, ENCD, pWenc_h, pWenc_l, ENCD, b_enc_att,
                                             p_encproj, AA, BB * LL, AA, ENCD);

    // ---- sequential loop: 2 launches per step
    for (int t = 0; t < TT; t++) {
        fused_step<<<BB, 256>>>(enc_out, W_dec_att, b_dec_att, w_full, b_full, alphas, t);
        gates_step<<<dim3(16, 8), 256, SMEM_GT>>>();
    }
    // final finalize (produces h_{T-1} into g_hall)
    fused_step<<<BB, 256>>>(enc_out, W_dec_att, b_dec_att, w_full, b_full, alphas, TT);

    // ---- batched logits (1280 x 10000) = hall @ Wout^T, (b,t) scatter + bias
    mma_gemm<1><<<dim3(79, 10), 256, 65536>>>(p_hall, DD, pWout_h, pWout_l, DD, b_out,
                                              out, VV, TT * BB, VV, DD);
}

// round 17
// speedup vs baseline: 1.5923x; 1.5923x over previous
#include <cuda_runtime.h>
#include <cuda_bf16.h>
#include <cstdint>
#include <cstddef>

// Problem constants
#define BB   64
#define LL   49
#define TT   20
#define VV   10000
#define EE   512
#define ENCD 2048
#define DD   512
#define AA   512
#define NG   2048
#define KC2  2560    // ENC + D

#define SMEMB 51200  // fp32 gemm dynamic smem

// ---------------- device scratch (static, no allocations) ----------------
__device__ float g_mean[BB * ENCD];
__device__ float g_encproj[BB * LL * AA];
__device__ float g_bcat[NG];
__device__ float g_Eall[TT * BB * EE];
__device__ float g_Gemb[TT * BB * NG];
__device__ float g_h[BB * DD];
__device__ float g_c[BB * DD];
__device__ float g_X2[BB * KC2];
__device__ float g_hall[TT * BB * DD];
__device__ float g_ph[8 * BB * DD];
__device__ float g_pc[8 * BB * DD];
__device__ float g_decp[8 * BB * AA];
__device__ float g_gpart[10 * BB * NG];
// pre-split bf16 weights (hi/lo), all K-contiguous rows
__device__ __nv_bfloat16 g_Wch_h[NG * KC2],  g_Wch_l[NG * KC2];    // (2048 x 2560)
__device__ __nv_bfloat16 g_Wout_h[VV * DD],  g_Wout_l[VV * DD];    // (10000 x 512)
__device__ __nv_bfloat16 g_Wenc_h[AA * ENCD], g_Wenc_l[AA * ENCD]; // (512 x 2048)
__device__ __nv_bfloat16 g_Wemb_h[NG * EE],  g_Wemb_l[NG * EE];    // (2048 x 512)

// ---------------- helpers ----------------
__device__ __forceinline__ uint32_t smem_u32(const void* p) {
    uint32_t a;
    asm("{ .reg .u64 t; cvta.to.shared.u64 t, %1; cvt.u32.u64 %0, t; }" : "=r"(a) : "l"(p));
    return a;
}
__device__ __forceinline__ uint32_t sw128(uint32_t off) { return off ^ ((off >> 3) & 0x70); }

__device__ __forceinline__ void split2(float x, float y, uint32_t& hi, uint32_t& lo) {
    __nv_bfloat16 hx = __float2bfloat16_rn(x), hy = __float2bfloat16_rn(y);
    __nv_bfloat16 lx = __float2bfloat16_rn(x - __bfloat162float(hx));
    __nv_bfloat16 ly = __float2bfloat16_rn(y - __bfloat162float(hy));
    __nv_bfloat162 h; h.x = hx; h.y = hy;
    __nv_bfloat162 l; l.x = lx; l.y = ly;
    hi = *(uint32_t*)&h;
    lo = *(uint32_t*)&l;
}

__device__ __forceinline__ void ldsm4(uint32_t a, uint32_t& r0, uint32_t& r1,
                                      uint32_t& r2, uint32_t& r3) {
    asm volatile("ldmatrix.sync.aligned.m8n8.x4.shared.b16 {%0,%1,%2,%3}, [%4];"
                 : "=r"(r0), "=r"(r1), "=r"(r2), "=r"(r3) : "r"(a));
}
__device__ __forceinline__ void mma16816(float* d, const uint32_t* a, const uint32_t* b) {
    asm volatile("mma.sync.aligned.m16n8k16.row.col.f32.bf16.bf16.f32 "
                 "{%0,%1,%2,%3}, {%4,%5,%6,%7}, {%8,%9}, {%0,%1,%2,%3};"
                 : "+f"(d[0]), "+f"(d[1]), "+f"(d[2]), "+f"(d[3])
                 : "r"(a[0]), "r"(a[1]), "r"(a[2]), "r"(a[3]), "r"(b[0]), "r"(b[1]));
}

// ---------------- mma.sync split-bf16 GEMM device body ----------------
template<int BM, int MODE>
__device__ void mma_gemm_dev(char* smem, int bx, int by, int bz, int gz,
                             const float* __restrict__ A, int lda,
                             const __nv_bfloat16* __restrict__ Bhi,
                             const __nv_bfloat16* __restrict__ Blo,
                             int ldb, const float* __restrict__ bias,
                             float* __restrict__ C, int ldc, int M, int N, int K)
{
    constexpr int ASZ = BM * 128;
    constexpr int NJ  = (BM == 128) ? 4 : 2;
    const uint32_t sb = smem_u32(smem);
    const uint32_t AHI = 0, ALO = ASZ, BHI = 2 * ASZ, BLO = 2 * ASZ + 16384;

    const int tid = threadIdx.x, lane = tid & 31, wid = tid >> 5;
    const int m0 = by * BM, n0 = bx * 128;
    const int kbase = bz * K;
    if (MODE == 0 && gz > 1) C += (size_t)bz * (size_t)M * (size_t)N;

    const int wm = (BM == 128) ? (wid & 3) * 32 : (wid & 1) * 32;
    const int wn = (BM == 128) ? (wid >> 2) * 64 : (wid >> 1) * 32;
    const int lr = lane & 7, lm = lane >> 3;

    float acc[2][2 * NJ][4];
    #pragma unroll
    for (int i = 0; i < 2; i++)
        #pragma unroll
        for (int j = 0; j < 2 * NJ; j++)
            #pragma unroll
            for (int q = 0; q < 4; q++) acc[i][j][q] = 0.f;

    for (int kc = 0; kc < K; kc += 64) {
        constexpr int AIT = BM / 32;
        #pragma unroll
        for (int p = 0; p < AIT; p++) {
            const int i = tid + 256 * p;
            const int row = i >> 3, c16 = i & 7;
            const int gm = m0 + row;
            float4 v0 = make_float4(0.f, 0.f, 0.f, 0.f), v1 = v0;
            if (gm < M) {
                const float* ap = A + (size_t)gm * lda + kbase + kc + c16 * 8;
                v0 = *(const float4*)ap;
                v1 = *(const float4*)(ap + 4);
            }
            uint4 hv, lv;
            split2(v0.x, v0.y, hv.x, lv.x);
            split2(v0.z, v0.w, hv.y, lv.y);
            split2(v1.x, v1.y, hv.z, lv.z);
            split2(v1.z, v1.w, hv.w, lv.w);
            const uint32_t so = sw128((uint32_t)(row * 128 + c16 * 16));
            *(uint4*)(smem + AHI + so) = hv;
            *(uint4*)(smem + ALO + so) = lv;
        }
        #pragma unroll
        for (int p = 0; p < 4; p++) {
            const int i = tid + 256 * p;
            const int row = i >> 3, c16 = i & 7;
            const int gn = n0 + row;
            uint4 vh = make_uint4(0, 0, 0, 0), vl = vh;
            if (gn < N) {
                vh = *(const uint4*)(Bhi + (size_t)gn * ldb + kbase + kc + c16 * 8);
                vl = *(const uint4*)(Blo + (size_t)gn * ldb + kbase + kc + c16 * 8);
            }
            const uint32_t so = sw128((uint32_t)(row * 128 + c16 * 16));
            *(uint4*)(smem + BHI + so) = vh;
            *(uint4*)(smem + BLO + so) = vl;
        }
        __syncthreads();

        #pragma unroll
        for (int kk = 0; kk < 4; kk++) {
            uint32_t ah[2][4], al[2][4];
            #pragma unroll
            for (int mt = 0; mt < 2; mt++) {
                const uint32_t off = sw128((uint32_t)(
                    (wm + mt * 16 + (lm & 1) * 8 + lr) * 128 + kk * 32 + (lm >> 1) * 16));
                ldsm4(sb + AHI + off, ah[mt][0], ah[mt][1], ah[mt][2], ah[mt][3]);
                ldsm4(sb + ALO + off, al[mt][0], al[mt][1], al[mt][2], al[mt][3]);
            }
            #pragma unroll
            for (int j = 0; j < NJ; j++) {
                const uint32_t offb = sw128((uint32_t)(
                    (wn + j * 16 + (lm >> 1) * 8 + lr) * 128 + kk * 32 + (lm & 1) * 16));
                uint32_t bh[4], bl[4];
                ldsm4(sb + BHI + offb, bh[0], bh[1], bh[2], bh[3]);
                ldsm4(sb + BLO + offb, bl[0], bl[1], bl[2], bl[3]);
                #pragma unroll
                for (int mt = 0; mt < 2; mt++) {
                    #pragma unroll
                    for (int h = 0; h < 2; h++) {
                        float* d = acc[mt][j * 2 + h];
                        mma16816(d, ah[mt], bh + 2 * h);
                        mma16816(d, ah[mt], bl + 2 * h);
                        mma16816(d, al[mt], bh + 2 * h);
                    }
                }
            }
        }
        __syncthreads();
    }

    const int r_lane = lane >> 2;
    const int c_lane = (lane & 3) * 2;
    #pragma unroll
    for (int mt = 0; mt < 2; mt++) {
        #pragma unroll
        for (int nt = 0; nt < 2 * NJ; nt++) {
            const int c = n0 + wn + nt * 8 + c_lane;
            if (c >= N) continue;
            const float b0 = bias ? bias[c] : 0.f;
            const float b1 = bias ? bias[c + 1] : 0.f;
            #pragma unroll
            for (int hh = 0; hh < 2; hh++) {
                const int r = m0 + wm + mt * 16 + r_lane + hh * 8;
                if (r >= M) continue;
                float2 v;
                v.x = acc[mt][nt][hh * 2 + 0] + b0;
                v.y = acc[mt][nt][hh * 2 + 1] + b1;
                if (MODE == 0) {
                    *(float2*)&C[(size_t)r * ldc + c] = v;
                } else {
                    const int tq = r >> 6, bq = r & 63;
                    *(float2*)&C[((size_t)bq * TT + tq) * VV + c] = v;
                }
            }
        }
    }
}

// ---------------- packed fp32x2 helpers ----------------
#define FMA2(D,Aq,Bq,Cq) asm("fma.rn.f32x2 %0, %1, %2, %3;" : "=l"(D) : "l"(Aq), "l"(Bq), "l"(Cq))
#define PACK2(D,LO,HI)   asm("mov.b64 %0, {%1, %2};" : "=l"(D) : "f"(LO), "f"(HI))
#define UNPK2(LO,HI,S)   asm("mov.b64 {%0, %1}, %2;" : "=f"(LO), "=f"(HI) : "l"(S))

// ---------------- fp32 FFMA2 GEMM device body (NN layout) ----------------
__device__ void gemm_f32_dev(float* sm, int bx, int by, int bz, int gz,
                             const float* __restrict__ A, int lda,
                             const float* __restrict__ B, int ldb,
                             float* __restrict__ C, int M, int N, int K)
{
    float* As = sm;
    float* Bs = sm + 2 * 32 * 68;

    const int tid = threadIdx.x;
    const int m0  = by * 64;
    const int n0  = bx * 128;
    const int k0base = bz * K;
    if (gz > 1) C += (size_t)bz * (size_t)M * (size_t)N;

    const int lane = tid & 31, warp = tid >> 5, tx = lane;
    const int a_kp = tid & 7, a_mr = tid >> 3;
    const int b_n4 = tid & 31, b_kr = tid >> 5;

    float4 Ag[2], Bg[4];
    const float4 z4 = make_float4(0.f, 0.f, 0.f, 0.f);

    unsigned long long acc2[4][4];
    #pragma unroll
    for (int i = 0; i < 4; i++)
        #pragma unroll
        for (int j = 0; j < 4; j++) acc2[i][j] = 0ull;

    {
        const int k0 = k0base;
        #pragma unroll
        for (int p = 0; p < 2; p++) {
            const int gm = m0 + a_mr + p * 32;
            Ag[p] = (gm < M) ? *(const float4*)(A + (size_t)gm * lda + k0 + a_kp * 4) : z4;
        }
        #pragma unroll
        for (int p = 0; p < 4; p++) {
            const int kk = b_kr + p * 8;
            const int gn = n0 + b_n4 * 4;
            Bg[p] = (gn + 3 < N) ? *(const float4*)(B + (size_t)(k0 + kk) * ldb + gn) : z4;
        }
        float* Ad = As;
        #pragma unroll
        for (int p = 0; p < 2; p++) {
            const int m = a_mr + p * 32;
            Ad[(a_kp * 4 + 0) * 68 + m] = Ag[p].x;
            Ad[(a_kp * 4 + 1) * 68 + m] = Ag[p].y;
            Ad[(a_kp * 4 + 2) * 68 + m] = Ag[p].z;
            Ad[(a_kp * 4 + 3) * 68 + m] = Ag[p].w;
        }
        float* Bd = Bs;
        #pragma unroll
        for (int p = 0; p < 4; p++)
            *(float4*)&Bd[(b_kr + p * 8) * 132 + b_n4 * 4] = Bg[p];
    }
    __syncthreads();

    int cur = 0;
    for (int kt = 0; kt < K; kt += 32) {
        const bool has_next = (kt + 32 < K);
        if (has_next) {
            const int k0 = k0base + kt + 32;
            #pragma unroll
            for (int p = 0; p < 2; p++) {
                const int gm = m0 + a_mr + p * 32;
                Ag[p] = (gm < M) ? *(const float4*)(A + (size_t)gm * lda + k0 + a_kp * 4) : z4;
            }
            #pragma unroll
            for (int p = 0; p < 4; p++) {
                const int kk = b_kr + p * 8;
                const int gn = n0 + b_n4 * 4;
                Bg[p] = (gn + 3 < N) ? *(const float4*)(B + (size_t)(k0 + kk) * ldb + gn) : z4;
            }
        }
        const float* Ab = As + cur * 2176;
        const float* Bb = Bs + cur * 4224;
        #pragma unroll
        for (int kk = 0; kk < 32; kk++) {
            const float* Ak = Ab + kk * 68 + warp * 8;
            const float* Bk = Bb + kk * 132 + tx * 4;
            ulonglong2 av0 = *(const ulonglong2*)(Ak);
            ulonglong2 av1 = *(const ulonglong2*)(Ak + 4);
            float4 bv = *(const float4*)(Bk);
            unsigned long long a2[4] = {av0.x, av0.y, av1.x, av1.y};
            unsigned long long b2[4];
            PACK2(b2[0], bv.x, bv.x);
            PACK2(b2[1], bv.y, bv.y);
            PACK2(b2[2], bv.z, bv.z);
            PACK2(b2[3], bv.w, bv.w);
            #pragma unroll
            for (int i = 0; i < 4; i++)
                #pragma unroll
                for (int j = 0; j < 4; j++)
                    FMA2(acc2[i][j], a2[i], b2[j], acc2[i][j]);
        }
        if (has_next) {
            const int nb = cur ^ 1;
            float* Ad = As + nb * 2176;
            #pragma unroll
            for (int p = 0; p < 2; p++) {
                const int m = a_mr + p * 32;
                Ad[(a_kp * 4 + 0) * 68 + m] = Ag[p].x;
                Ad[(a_kp * 4 + 1) * 68 + m] = Ag[p].y;
                Ad[(a_kp * 4 + 2) * 68 + m] = Ag[p].z;
                Ad[(a_kp * 4 + 3) * 68 + m] = Ag[p].w;
            }
            float* Bd = Bs + nb * 4224;
            #pragma unroll
            for (int p = 0; p < 4; p++)
                *(float4*)&Bd[(b_kr + p * 8) * 132 + b_n4 * 4] = Bg[p];
        }
        __syncthreads();
        cur ^= 1;
    }

    #pragma unroll
    for (int ip = 0; ip < 4; ip++) {
        const int r0 = m0 + warp * 8 + ip * 2;
        #pragma unroll
        for (int j = 0; j < 4; j++) {
            const int c = n0 + tx * 4 + j;
            if (c >= N) continue;
            float v0, v1;
            UNPK2(v0, v1, acc2[ip][j]);
            if (r0 < M)     C[(size_t)r0 * N + c]       = v0;
            if (r0 + 1 < M) C[(size_t)(r0 + 1) * N + c] = v1;
        }
    }
}

// ---------------- global wrappers for loop / logits ----------------
__global__ void __launch_bounds__(256)
gemm_f32_kernel(const float* A, int lda, const float* B, int ldb,
                float* C, int M, int N, int K)
{
    extern __shared__ float smf[];
    gemm_f32_dev(smf, blockIdx.x, blockIdx.y, blockIdx.z, gridDim.z,
                 A, lda, B, ldb, C, M, N, K);
}

__global__ void __launch_bounds__(256)
gates_kernel(const float* A, const __nv_bfloat16* Bhi, const __nv_bfloat16* Blo)
{
    extern __shared__ __align__(1024) char smem[];
    mma_gemm_dev<64, 0>(smem, blockIdx.x, 0, blockIdx.z, gridDim.z,
                        A, KC2, Bhi, Blo, KC2, nullptr,
                        (float*)g_gpart, NG, BB, NG, 256);
}

__global__ void __launch_bounds__(256)
logits_kernel(const float* A, const __nv_bfloat16* Bhi, const __nv_bfloat16* Blo,
              const float* bias, float* C)
{
    extern __shared__ __align__(1024) char smem[];
    mma_gemm_dev<128, 1>(smem, blockIdx.x, blockIdx.y, 0, 1,
                         A, DD, Bhi, Blo, DD, bias, C, VV, TT * BB, VV, DD);
}

// ---------------- mega setup 1 ----------------
__device__ void transpose_dev(const float* __restrict__ in,
                              __nv_bfloat16* __restrict__ oh,
                              __nv_bfloat16* __restrict__ ol,
                              int Kd, int Nd, int bx, int by, float (*tile)[33])
{
    const int tx = threadIdx.x & 31, ty = threadIdx.x >> 5;  // 32 x 8
    const int kb = by * 32, nb = bx * 32;
    #pragma unroll
    for (int p = 0; p < 4; p++) {
        const int k = kb + ty + p * 8, n = nb + tx;
        if (k < Kd && n < Nd) tile[ty + p * 8][tx] = in[(size_t)k * Nd + n];
    }
    __syncthreads();
    #pragma unroll
    for (int p = 0; p < 4; p++) {
        const int n = nb + ty + p * 8, k = kb + tx;
        if (n < Nd && k < Kd) {
            float v = tile[tx][ty + p * 8];
            __nv_bfloat16 h = __float2bfloat16_rn(v);
            oh[(size_t)n * Kd + k] = h;
            ol[(size_t)n * Kd + k] = __float2bfloat16_rn(v - __bfloat162float(h));
        }
    }
}

__global__ void __launch_bounds__(256)
mega_setup1(const float* __restrict__ W_ih, const float* __restrict__ W_hh,
            const float* __restrict__ b_ih, const float* __restrict__ b_hh,
            const int* __restrict__ captions, const float* __restrict__ emb_table,
            const float* __restrict__ W_enc_att, const float* __restrict__ W_out,
            const float* __restrict__ enc_out)
{
    __shared__ float tile[32][33];
    const int blk = blockIdx.x, tid = threadIdx.x;

    if (blk < 2048) {
        const long total = (long)NG * KC2;
        for (long idx = (long)blk * 256 + tid; idx < total; idx += 2048L * 256) {
            int j = (int)(idx / KC2);
            int k = (int)(idx % KC2);
            float v = (k < ENCD) ? W_ih[(size_t)j * 2560 + 512 + k]
                                 : W_hh[(size_t)j * 512 + (k - ENCD)];
            __nv_bfloat16 h = __float2bfloat16_rn(v);
            g_Wch_h[idx] = h;
            g_Wch_l[idx] = __float2bfloat16_rn(v - __bfloat162float(h));
        }
        int gidx = blk * 256 + tid;
        if (gidx < NG) g_bcat[gidx] = b_ih[gidx] + b_hh[gidx];
    } else if (blk < 2560) {
        const int q = blk - 2048;
        const long te = (long)NG * EE;
        for (long idx = (long)q * 256 + tid; idx < te; idx += 512L * 256) {
            int j = (int)(idx / EE);
            int e = (int)(idx % EE);
            float v = W_ih[(size_t)j * 2560 + e];
            __nv_bfloat16 h = __float2bfloat16_rn(v);
            g_Wemb_h[idx] = h;
            g_Wemb_l[idx] = __float2bfloat16_rn(v - __bfloat162float(h));
        }
    } else if (blk < 2880) {
        const int q = blk - 2560;
        for (int idx = q * 256 + tid; idx < TT * BB * EE; idx += 320 * 256) {
            int e  = idx & 511;
            int rb = idx >> 9;
            int tq = rb >> 6, bq = rb & 63;
            g_Eall[idx] = emb_table[(size_t)captions[bq * TT + tq] * EE + e];
        }
    } else if (blk < 3904) {
        const int q = blk - 2880;
        transpose_dev(W_enc_att, g_Wenc_h, g_Wenc_l, ENCD, AA, q % 16, q / 16, tile);
    } else if (blk < 8912) {
        const int q = blk - 3904;
        transpose_dev(W_out, g_Wout_h, g_Wout_l, DD, VV, q % 313, q / 313, tile);
    } else {
        const int b = blk - 8912;
        for (int e = tid; e < ENCD; e += 256) {
            const float* p = enc_out + (size_t)b * LL * ENCD + e;
            float s = 0.f;
            #pragma unroll 7
            for (int l = 0; l < LL; l++) s += p[(size_t)l * ENCD];
            g_mean[b * ENCD + e] = s * (1.f / (float)LL);
        }
    }
}

// ---------------- mega setup 2 ----------------
__global__ void __launch_bounds__(256)
mega_setup2(const float* __restrict__ enc_out, const float* __restrict__ b_enc_att,
            const float* __restrict__ W_init_h, const float* __restrict__ W_init_c)
{
    extern __shared__ __align__(1024) char smem[];
    const int blk = blockIdx.x;
    if (blk < 160) {
        mma_gemm_dev<128, 0>(smem, blk % 16, blk / 16, 0, 1,
                             (const float*)g_Eall, EE, g_Wemb_h, g_Wemb_l, EE, nullptr,
                             (float*)g_Gemb, NG, TT * BB, NG, EE);
    } else if (blk < 260) {
        const int q = blk - 160;
        mma_gemm_dev<128, 0>(smem, q % 4, q / 4, 0, 1,
                             enc_out, ENCD, g_Wenc_h, g_Wenc_l, ENCD, b_enc_att,
                             (float*)g_encproj, AA, BB * LL, AA, ENCD);
    } else if (blk < 292) {
        const int q = blk - 260;
        gemm_f32_dev((float*)smem, q % 4, 0, q / 4, 8,
                     (const float*)g_mean, ENCD, W_init_h, DD, (float*)g_ph, BB, DD, 256);
    } else {
        const int q = blk - 292;
        gemm_f32_dev((float*)smem, q % 4, 0, q / 4, 8,
                     (const float*)g_mean, ENCD, W_init_c, DD, (float*)g_pc, BB, DD, 256);
    }
}

// ---------------- small kernels ----------------
__global__ void init_reduce(const float* __restrict__ b_init_h,
                            const float* __restrict__ b_init_c)
{
    int idx = blockIdx.x * blockDim.x + threadIdx.x;
    int b = idx >> 9, d = idx & 511;
    float h = b_init_h[d], c = b_init_c[d];
    #pragma unroll
    for (int z = 0; z < 8; z++) {
        h += g_ph[z * (BB * DD) + idx];
        c += g_pc[z * (BB * DD) + idx];
    }
    g_h[idx] = h;
    g_c[idx] = c;
    g_X2[(size_t)b * KC2 + ENCD + d] = h;
}

__device__ __forceinline__ float sigmoidf(float x) { return 1.f / (1.f + expf(-x)); }

__global__ void lstm_finalize(int t)
{
    int idx = blockIdx.x * blockDim.x + threadIdx.x;
    int b = idx >> 9, d = idx & 511;
    const float* ge = g_Gemb + ((size_t)t * BB + b) * NG;
    float gi = g_bcat[d]        + ge[d];
    float gf = g_bcat[512 + d]  + ge[512 + d];
    float gg = g_bcat[1024 + d] + ge[1024 + d];
    float go = g_bcat[1536 + d] + ge[1536 + d];
    #pragma unroll
    for (int z = 0; z < 10; z++) {
        const float* p = g_gpart + ((size_t)z * BB + b) * NG;
        gi += p[d]; gf += p[512 + d]; gg += p[1024 + d]; go += p[1536 + d];
    }
    float i = sigmoidf(gi), f = sigmoidf(gf), o = sigmoidf(go), g = tanhf(gg);
    float c = f * g_c[idx] + i * g;
    float h = o * tanhf(c);
    g_c[idx] = c;
    g_h[idx] = h;
    g_X2[(size_t)b * KC2 + ENCD + d] = h;
    g_hall[((size_t)t * BB + b) * DD + d] = h;
}

// ---------------- attention (vectorized scores + context) ----------------
__global__ void att_kernel(const float* __restrict__ enc_out,
                           const float* __restrict__ b_dec_att,
                           const float* __restrict__ w_full,
                           const float* __restrict__ b_full,
                           float* __restrict__ alphas_out, int t)
{
    __shared__ float sh_dec[AA];
    __shared__ float sh_w[AA];
    __shared__ float sh_sc[64];

    const int b = blockIdx.x, tid = threadIdx.x;
    for (int a = tid; a < AA; a += 256) {
        float s = b_dec_att[a];
        #pragma unroll
        for (int z = 0; z < 8; z++) s += g_decp[((size_t)z * BB + b) * AA + a];
        sh_dec[a] = s;
        sh_w[a]   = w_full[a];
    }
    __syncthreads();

    const int warp = tid >> 5, lane = tid & 31;
    for (int l = warp; l < LL; l += 8) {
        const float4* ep = (const float4*)(g_encproj + ((size_t)b * LL + l) * AA);
        float s = 0.f;
        #pragma unroll
        for (int a4 = lane; a4 < 128; a4 += 32) {
            float4 e4 = ep[a4];
            float4 dv = *(const float4*)&sh_dec[a4 * 4];
            float4 wv = *(const float4*)&sh_w[a4 * 4];
            s = fmaf(fmaxf(e4.x + dv.x, 0.f), wv.x, s);
            s = fmaf(fmaxf(e4.y + dv.y, 0.f), wv.y, s);
            s = fmaf(fmaxf(e4.z + dv.z, 0.f), wv.z, s);
            s = fmaf(fmaxf(e4.w + dv.w, 0.f), wv.w, s);
        }
        #pragma unroll
        for (int o = 16; o; o >>= 1) s += __shfl_xor_sync(0xffffffffu, s, o);
        if (lane == 0) sh_sc[l] = s + b_full[0];
    }
    __syncthreads();

    if (warp == 0) {
        float v0 = (lane < LL) ? sh_sc[lane] : -1e30f;
        float v1 = (lane + 32 < LL) ? sh_sc[lane + 32] : -1e30f;
        float mx = fmaxf(v0, v1);
        #pragma unroll
        for (int o = 16; o; o >>= 1) mx = fmaxf(mx, __shfl_xor_sync(0xffffffffu, mx, o));
        float e0 = (lane < LL) ? expf(v0 - mx) : 0.f;
        float e1 = (lane + 32 < LL) ? expf(v1 - mx) : 0.f;
        float ssum = e0 + e1;
        #pragma unroll
        for (int o = 16; o; o >>= 1) ssum += __shfl_xor_sync(0xffffffffu, ssum, o);
        float inv = 1.f / ssum;
        if (lane < LL) sh_sc[lane] = e0 * inv;
        if (lane + 32 < LL) sh_sc[lane + 32] = e1 * inv;
    }
    __syncthreads();

    for (int l = tid; l < LL; l += 256)
        alphas_out[((size_t)b * TT + t) * LL + l] = sh_sc[l];

    #pragma unroll
    for (int rep = 0; rep < 2; rep++) {
        const int e4 = tid + rep * 256;
        const float4* eb = (const float4*)(enc_out + (size_t)b * LL * ENCD) + e4;
        float4 s = make_float4(0.f, 0.f, 0.f, 0.f);
        #pragma unroll 7
        for (int l = 0; l < LL; l++) {
            float4 v = eb[(size_t)l * (ENCD / 4)];
            float al = sh_sc[l];
            s.x = fmaf(al, v.x, s.x);
            s.y = fmaf(al, v.y, s.y);
            s.z = fmaf(al, v.z, s.z);
            s.w = fmaf(al, v.w, s.w);
        }
        *(float4*)&g_X2[(size_t)b * KC2 + e4 * 4] = s;
    }
}

// ---------------- host launch ----------------
extern "C" void kernel_launch(void* const* d_in, const int* in_sizes, int n_in,
                              void* d_out, int out_size)
{
    const float* enc_out    = (const float*)d_in[0];
    const int*   captions   = (const int*)  d_in[1];
    const float* emb_table  = (const float*)d_in[2];
    const float* W_enc_att  = (const float*)d_in[3];
    const float* b_enc_att  = (const float*)d_in[4];
    const float* W_dec_att  = (const float*)d_in[5];
    const float* b_dec_att  = (const float*)d_in[6];
    const float* w_full     = (const float*)d_in[7];
    const float* b_full     = (const float*)d_in[8];
    const float* W_ih       = (const float*)d_in[9];
    const float* b_ih       = (const float*)d_in[10];
    const float* W_hh       = (const float*)d_in[11];
    const float* b_hh       = (const float*)d_in[12];
    const float* W_init_h   = (const float*)d_in[13];
    const float* b_init_h   = (const float*)d_in[14];
    const float* W_init_c   = (const float*)d_in[15];
    const float* b_init_c   = (const float*)d_in[16];
    const float* W_out      = (const float*)d_in[17];
    const float* b_out      = (const float*)d_in[18];
    float* out = (float*)d_out;
    float* alphas = out + (size_t)BB * TT * VV;

    cudaFuncSetAttribute(gemm_f32_kernel, cudaFuncAttributeMaxDynamicSharedMemorySize, SMEMB);
    cudaFuncSetAttribute(gates_kernel,  cudaFuncAttributeMaxDynamicSharedMemorySize, 49152);
    cudaFuncSetAttribute(logits_kernel, cudaFuncAttributeMaxDynamicSharedMemorySize, 65536);
    cudaFuncSetAttribute(mega_setup2,   cudaFuncAttributeMaxDynamicSharedMemorySize, 65536);

    float *p_h, *p_X2, *p_hall, *p_decp;
    __nv_bfloat16 *pWch_h, *pWch_l, *pWout_h, *pWout_l;
    cudaGetSymbolAddress((void**)&p_h,     g_h);
    cudaGetSymbolAddress((void**)&p_X2,    g_X2);
    cudaGetSymbolAddress((void**)&p_hall,  g_hall);
    cudaGetSymbolAddress((void**)&p_decp,  g_decp);
    cudaGetSymbolAddress((void**)&pWch_h,  g_Wch_h);
    cudaGetSymbolAddress((void**)&pWch_l,  g_Wch_l);
    cudaGetSymbolAddress((void**)&pWout_h, g_Wout_h);
    cudaGetSymbolAddress((void**)&pWout_l, g_Wout_l);

    // ---- setup: 3 launches, all internal work concurrent within each
    mega_setup1<<<8976, 256>>>(W_ih, W_hh, b_ih, b_hh, captions, emb_table,
                               W_enc_att, W_out, enc_out);
    mega_setup2<<<324, 256, 65536>>>(enc_out, b_enc_att, W_init_h, W_init_c);
    init_reduce<<<128, 256>>>(b_init_h, b_init_c);

    // ---- sequential loop (R7 structure: 4 launches per step)
    for (int t = 0; t < TT; t++) {
        // dec_proj partials (64x512) = h @ W_dec_att, split-K 8
        gemm_f32_kernel<<<dim3(4, 1, 8), 256, SMEMB>>>(p_h, DD, W_dec_att, AA,
                                                       p_decp, BB, AA, 64);
        att_kernel<<<BB, 256>>>(enc_out, b_dec_att, w_full, b_full, alphas, t);
        // gates partials (64x2048) = X2 @ Wch^T, split-K 10 (Kc=256)
        gates_kernel<<<dim3(16, 1, 10), 256, 49152>>>(p_X2, pWch_h, pWch_l);
        lstm_finalize<<<128, 256>>>(t);
    }

    // ---- batched logits (1280 x 10000) = hall @ Wout^T, (b,t) scatter + bias
    logits_kernel<<<dim3(79, 10), 256, 65536>>>(p_hall, pWout_h, pWout_l, b_out, out);
}